// round 10
// baseline (speedup 1.0000x reference)
#include <cuda_runtime.h>
#include <cuda_fp16.h>
#include <cstddef>
#include <cstdint>

#define BB 16
#define TT 2048
#define CC 1024
#define HH 64
#define MM (BB*TT)   // 32768 rows

// fp16 scratch (Q pre-scaled by C^-0.5 * log2(e)); 16B-aligned for vector/cp.async
__device__ __align__(256) __half g_Q[(size_t)MM*HH];
__device__ __align__(256) __half g_K[(size_t)MM*HH];
__device__ __align__(256) __half g_V[(size_t)MM*HH];
__device__ __align__(256) __half g_Wh[(size_t)CC*192];   // [k][n], n = 3*64

// ---------------------------------------------------------------------------
// helpers
// ---------------------------------------------------------------------------
__device__ __forceinline__ uint32_t smem_u32(const void* p) {
    return (uint32_t)__cvta_generic_to_shared(p);
}

__device__ __forceinline__ void ldsm4(uint32_t addr, unsigned& r0, unsigned& r1,
                                      unsigned& r2, unsigned& r3) {
    asm volatile("ldmatrix.sync.aligned.m8n8.x4.shared.b16 {%0,%1,%2,%3}, [%4];"
                 : "=r"(r0), "=r"(r1), "=r"(r2), "=r"(r3) : "r"(addr));
}

__device__ __forceinline__ void ldsm4t(uint32_t addr, unsigned& r0, unsigned& r1,
                                       unsigned& r2, unsigned& r3) {
    asm volatile("ldmatrix.sync.aligned.m8n8.x4.trans.shared.b16 {%0,%1,%2,%3}, [%4];"
                 : "=r"(r0), "=r"(r1), "=r"(r2), "=r"(r3) : "r"(addr));
}

__device__ __forceinline__ void mma16816(float* d, const unsigned* a,
                                         unsigned b0, unsigned b1, const float* c) {
    asm volatile(
        "mma.sync.aligned.m16n8k16.row.col.f32.f16.f16.f32 "
        "{%0,%1,%2,%3}, {%4,%5,%6,%7}, {%8,%9}, {%10,%11,%12,%13};"
        : "=f"(d[0]), "=f"(d[1]), "=f"(d[2]), "=f"(d[3])
        : "r"(a[0]), "r"(a[1]), "r"(a[2]), "r"(a[3]),
          "r"(b0), "r"(b1),
          "f"(c[0]), "f"(c[1]), "f"(c[2]), "f"(c[3]));
}

__device__ __forceinline__ float ex2(float x) {
    float y;
    asm("ex2.approx.ftz.f32 %0, %1;" : "=f"(y) : "f"(x));
    return y;
}

__device__ __forceinline__ void cp16(uint32_t dst, const void* src) {
    asm volatile("cp.async.cg.shared.global [%0], [%1], 16;" :: "r"(dst), "l"(src));
}
#define CP_COMMIT() asm volatile("cp.async.commit_group;")
#define CP_WAIT(N)  asm volatile("cp.async.wait_group %0;" :: "n"(N))

__device__ __forceinline__ unsigned h2u(__half2 h) {
    return *reinterpret_cast<unsigned*>(&h);
}

// ---------------------------------------------------------------------------
// Kernel 0: pack Wq|Wk|Wv into fp16 [k][192] once (L2-resident thereafter).
// ---------------------------------------------------------------------------
__global__ __launch_bounds__(256) void wprep_kernel(
    const float* __restrict__ Wq,
    const float* __restrict__ Wk,
    const float* __restrict__ Wv)
{
    int idx = blockIdx.x * 256 + threadIdx.x;      // 0 .. CC*192-1
    int k = idx / 192, n = idx % 192;
    int mat = n >> 6, col = n & 63;
    const float* W = (mat == 0) ? Wq : (mat == 1) ? Wk : Wv;
    g_Wh[idx] = __float2half(W[(size_t)k * HH + col]);
}

// ---------------------------------------------------------------------------
// Kernel 1: fused QKV projection. CTA: 256 thr (8 warps: 4m x 2n),
// tile 64m x 192n, BK=32. x reg-staged; W via cp.async double-buffer (fp16).
// ---------------------------------------------------------------------------
__global__ __launch_bounds__(256, 3) void qkv_kernel(const float* __restrict__ x)
{
    __shared__ __half As[64][40];        // [m][k]
    __shared__ __half Bs[2][32][200];    // [k][n]  n=192 + pad 8

    const int tid  = threadIdx.x;
    const int lane = tid & 31;
    const int wid  = tid >> 5;
    const int wm   = wid & 3;        // m strip of 16
    const int wn   = wid >> 2;       // n half of 96
    const int sub  = lane >> 3;
    const int rr   = lane & 7;
    const int g    = lane >> 2;
    const int t    = lane & 3;
    const int m0   = blockIdx.x * 64;

    const int a_row = tid >> 3, a_c4 = tid & 7;    // x tile mapping (+i*32 rows)

    // Wh chunk mapping: 32 rows x 24 chunks(16B) = 768, 3 per thread
    int w_row[3], w_c[3];
    #pragma unroll
    for (int j = 0; j < 3; j++) {
        int i = tid + j * 256;
        w_row[j] = i / 24; w_c[j] = i % 24;
    }

    float acc[12][4];
    #pragma unroll
    for (int nt = 0; nt < 12; nt++)
        #pragma unroll
        for (int e = 0; e < 4; e++) acc[nt][e] = 0.f;

    // prologue: x(k0=0) -> regs, Wh(k0=0) -> Bs[0]
    float4 ax[2];
    #pragma unroll
    for (int i = 0; i < 2; i++)
        ax[i] = *(const float4*)&x[(size_t)(m0 + a_row + i * 32) * CC + a_c4 * 4];
    #pragma unroll
    for (int j = 0; j < 3; j++)
        cp16(smem_u32(&Bs[0][w_row[j]][w_c[j] * 8]),
             &g_Wh[(size_t)w_row[j] * 192 + w_c[j] * 8]);
    CP_COMMIT();

    for (int k0 = 0; k0 < CC; k0 += 32) {
        const int c = (k0 >> 5) & 1;

        // staged x -> As
        #pragma unroll
        for (int i = 0; i < 2; i++) {
            __half2* p = (__half2*)&As[a_row + i * 32][a_c4 * 4];
            p[0] = __floats2half2_rn(ax[i].x, ax[i].y);
            p[1] = __floats2half2_rn(ax[i].z, ax[i].w);
        }
        CP_WAIT(0);          // Bs[c] landed
        __syncthreads();

        // issue next tile: x -> regs, Wh -> Bs[c^1]
        if (k0 + 32 < CC) {
            #pragma unroll
            for (int i = 0; i < 2; i++)
                ax[i] = *(const float4*)&x[(size_t)(m0 + a_row + i * 32) * CC
                                           + k0 + 32 + a_c4 * 4];
            #pragma unroll
            for (int j = 0; j < 3; j++)
                cp16(smem_u32(&Bs[c ^ 1][w_row[j]][w_c[j] * 8]),
                     &g_Wh[(size_t)(k0 + 32 + w_row[j]) * 192 + w_c[j] * 8]);
            CP_COMMIT();
        }

        // compute
        #pragma unroll
        for (int kt = 0; kt < 2; kt++) {
            unsigned a[4];
            uint32_t ad = smem_u32(&As[wm * 16 + (sub & 1) * 8 + rr]
                                      [kt * 16 + (sub >> 1) * 8]);
            ldsm4(ad, a[0], a[1], a[2], a[3]);
            #pragma unroll
            for (int p = 0; p < 6; p++) {
                unsigned b0, b1, b2, b3;
                uint32_t bd = smem_u32(&Bs[c][kt * 16 + (sub & 1) * 8 + rr]
                                          [wn * 96 + p * 16 + (sub >> 1) * 8]);
                ldsm4t(bd, b0, b1, b2, b3);
                mma16816(acc[2 * p    ], a, b0, b1, acc[2 * p    ]);
                mma16816(acc[2 * p + 1], a, b2, b3, acc[2 * p + 1]);
            }
        }
        __syncthreads();
    }

    // epilogue: fp16 stores (Q pre-scaled)
    const float QS = 0.03125f * 1.44269504f;
    #pragma unroll
    for (int nt = 0; nt < 12; nt++) {
        int n = wn * 96 + nt * 8 + 2 * t;
        int mat = n >> 6, col = n & 63;
        __half* O = (mat == 0) ? g_Q : (mat == 1) ? g_K : g_V;
        float sc = (mat == 0) ? QS : 1.f;
        int row = m0 + wm * 16 + g;
        *(__half2*)&O[(size_t)row * HH + col] =
            __floats2half2_rn(acc[nt][0] * sc, acc[nt][1] * sc);
        *(__half2*)&O[(size_t)(row + 8) * HH + col] =
            __floats2half2_rn(acc[nt][2] * sc, acc[nt][3] * sc);
    }
}

// ---------------------------------------------------------------------------
// Kernel 2: causal flash attention. CTA: 128 thr (4 warps), BM=64, BN=64,
// register-resident P, cp.async double-buffered K/V.
// grid (32, 16); it = 31 - blockIdx.x (heavy tiles launch first).
// All 512 CTAs co-resident at 4 CTAs/SM.
// ---------------------------------------------------------------------------
__global__ __launch_bounds__(128, 4) void attn_kernel(float* __restrict__ out)
{
    __shared__ __half Qs[64][72];
    __shared__ __half Ks[2][64][72];
    __shared__ __half Vs[2][64][72];

    const int tid  = threadIdx.x;
    const int lane = tid & 31;
    const int wid  = tid >> 5;        // q rows [16w, 16w+16)
    const int sub  = lane >> 3;
    const int rr   = lane & 7;
    const int g    = lane >> 2;
    const int t    = lane & 3;
    const int b    = blockIdx.y;
    const int it   = 31 - (int)blockIdx.x;     // heavy first

    const size_t base = (size_t)b * TT * HH;
    const int row0 = wid * 16;
    const int qrow = row0 + g;

    const int kv_r = tid >> 3;
    const int kv_c = tid & 7;

    // stage 0 K/V via cp.async
    {
        const size_t ga = base + (size_t)kv_r * HH + kv_c * 8;
        #pragma unroll
        for (int i = 0; i < 4; i++) {
            cp16(smem_u32(&Ks[0][kv_r + i * 16][kv_c * 8]),
                 &g_K[ga + (size_t)i * 16 * HH]);
            cp16(smem_u32(&Vs[0][kv_r + i * 16][kv_c * 8]),
                 &g_V[ga + (size_t)i * 16 * HH]);
        }
    }
    CP_COMMIT();

    // load Q tile
    #pragma unroll
    for (int i = 0; i < 4; i++) {
        int idx = tid + i * 128;
        int r = idx >> 3, c = idx & 7;
        *(uint4*)&Qs[r][c * 8] =
            *(const uint4*)&g_Q[base + (size_t)(it * 64 + r) * HH + c * 8];
    }
    __syncthreads();

    unsigned aq[4][4];
    #pragma unroll
    for (int kt = 0; kt < 4; kt++) {
        uint32_t ad = smem_u32(&Qs[row0 + (sub & 1) * 8 + rr]
                                  [kt * 16 + (sub >> 1) * 8]);
        ldsm4(ad, aq[kt][0], aq[kt][1], aq[kt][2], aq[kt][3]);
    }

    float o[8][4];
    #pragma unroll
    for (int nt = 0; nt < 8; nt++)
        #pragma unroll
        for (int e = 0; e < 4; e++) o[nt][e] = 0.f;
    float m0r = -1e30f, m1r = -1e30f, l0r = 0.f, l1r = 0.f;

    for (int jt = 0; jt <= it; jt++) {
        const int cur = jt & 1;

        if (jt < it) {   // prefetch next stage
            const size_t ga = base + (size_t)((jt + 1) * 64 + kv_r) * HH + kv_c * 8;
            #pragma unroll
            for (int i = 0; i < 4; i++) {
                cp16(smem_u32(&Ks[cur ^ 1][kv_r + i * 16][kv_c * 8]),
                     &g_K[ga + (size_t)i * 16 * HH]);
                cp16(smem_u32(&Vs[cur ^ 1][kv_r + i * 16][kv_c * 8]),
                     &g_V[ga + (size_t)i * 16 * HH]);
            }
            CP_COMMIT();
            CP_WAIT(1);
        } else {
            CP_WAIT(0);
        }
        __syncthreads();

        // S = Q @ K^T
        float s[8][4];
        #pragma unroll
        for (int nt = 0; nt < 8; nt++)
            #pragma unroll
            for (int e = 0; e < 4; e++) s[nt][e] = 0.f;

        #pragma unroll
        for (int kt = 0; kt < 4; kt++) {
            #pragma unroll
            for (int p = 0; p < 4; p++) {
                unsigned b0, b1, b2, b3;
                uint32_t kd = smem_u32(&Ks[cur][p * 16 + (sub >> 1) * 8 + rr]
                                          [kt * 16 + (sub & 1) * 8]);
                ldsm4(kd, b0, b1, b2, b3);
                mma16816(s[2 * p    ], aq[kt], b0, b1, s[2 * p    ]);
                mma16816(s[2 * p + 1], aq[kt], b2, b3, s[2 * p + 1]);
            }
        }

        // causal mask (diagonal tile only)
        if (jt == it) {
            #pragma unroll
            for (int nt = 0; nt < 8; nt++) {
                int c = nt * 8 + 2 * t;
                if (c     > qrow    ) s[nt][0] = -1e30f;
                if (c + 1 > qrow    ) s[nt][1] = -1e30f;
                if (c     > qrow + 8) s[nt][2] = -1e30f;
                if (c + 1 > qrow + 8) s[nt][3] = -1e30f;
            }
        }

        // online softmax (base-2; Q pre-scaled by log2 e)
        float mx0 = -1e30f, mx1 = -1e30f;
        #pragma unroll
        for (int nt = 0; nt < 8; nt++) {
            mx0 = fmaxf(mx0, fmaxf(s[nt][0], s[nt][1]));
            mx1 = fmaxf(mx1, fmaxf(s[nt][2], s[nt][3]));
        }
        mx0 = fmaxf(mx0, __shfl_xor_sync(0xffffffffu, mx0, 1));
        mx0 = fmaxf(mx0, __shfl_xor_sync(0xffffffffu, mx0, 2));
        mx1 = fmaxf(mx1, __shfl_xor_sync(0xffffffffu, mx1, 1));
        mx1 = fmaxf(mx1, __shfl_xor_sync(0xffffffffu, mx1, 2));

        float mn0 = fmaxf(m0r, mx0), mn1 = fmaxf(m1r, mx1);
        float al0 = ex2(m0r - mn0), al1 = ex2(m1r - mn1);
        float sum0 = 0.f, sum1 = 0.f;
        __half2 ph0[8], ph1[8];
        #pragma unroll
        for (int nt = 0; nt < 8; nt++) {
            s[nt][0] = ex2(s[nt][0] - mn0);
            s[nt][1] = ex2(s[nt][1] - mn0);
            s[nt][2] = ex2(s[nt][2] - mn1);
            s[nt][3] = ex2(s[nt][3] - mn1);
            sum0 += s[nt][0] + s[nt][1];
            sum1 += s[nt][2] + s[nt][3];
            ph0[nt] = __floats2half2_rn(s[nt][0], s[nt][1]);
            ph1[nt] = __floats2half2_rn(s[nt][2], s[nt][3]);
        }
        sum0 += __shfl_xor_sync(0xffffffffu, sum0, 1);
        sum0 += __shfl_xor_sync(0xffffffffu, sum0, 2);
        sum1 += __shfl_xor_sync(0xffffffffu, sum1, 1);
        sum1 += __shfl_xor_sync(0xffffffffu, sum1, 2);
        m0r = mn0; m1r = mn1;
        l0r = l0r * al0 + sum0;
        l1r = l1r * al1 + sum1;
        #pragma unroll
        for (int nt = 0; nt < 8; nt++) {
            o[nt][0] *= al0; o[nt][1] *= al0;
            o[nt][2] *= al1; o[nt][3] *= al1;
        }

        // O += P @ V   (P register-resident: C-frag == A-frag layout)
        #pragma unroll
        for (int kt = 0; kt < 4; kt++) {
            unsigned pa[4] = { h2u(ph0[2 * kt]),     h2u(ph1[2 * kt]),
                               h2u(ph0[2 * kt + 1]), h2u(ph1[2 * kt + 1]) };
            #pragma unroll
            for (int p = 0; p < 4; p++) {
                unsigned v0, v1, v2, v3;
                uint32_t vd = smem_u32(&Vs[cur][kt * 16 + (sub & 1) * 8 + rr]
                                          [p * 16 + (sub >> 1) * 8]);
                ldsm4t(vd, v0, v1, v2, v3);
                mma16816(o[2 * p    ], pa, v0, v1, o[2 * p    ]);
                mma16816(o[2 * p + 1], pa, v2, v3, o[2 * p + 1]);
            }
        }
        __syncthreads();   // all warps done with buf[cur] before refill
    }

    // epilogue
    float inv0 = 1.f / l0r, inv1 = 1.f / l1r;
    int r0 = it * 64 + qrow;
    #pragma unroll
    for (int nt = 0; nt < 8; nt++) {
        int c = nt * 8 + 2 * t;
        float2 v0 = {o[nt][0] * inv0, o[nt][1] * inv0};
        float2 v1 = {o[nt][2] * inv1, o[nt][3] * inv1};
        *(float2*)&out[base + (size_t)r0 * HH + c]       = v0;
        *(float2*)&out[base + (size_t)(r0 + 8) * HH + c] = v1;
    }
}

// ---------------------------------------------------------------------------
extern "C" void kernel_launch(void* const* d_in, const int* in_sizes, int n_in,
                              void* d_out, int out_size)
{
    const float* x  = (const float*)d_in[0];
    const float* Wq = (const float*)d_in[1];
    const float* Wk = (const float*)d_in[2];
    const float* Wv = (const float*)d_in[3];
    float* out = (float*)d_out;

    wprep_kernel<<<CC * 192 / 256, 256>>>(Wq, Wk, Wv);
    qkv_kernel<<<MM / 64, 256>>>(x);
    attn_kernel<<<dim3(32, BB), 128>>>(out);
}

// round 12
// speedup vs baseline: 1.2065x; 1.2065x over previous
#include <cuda_runtime.h>
#include <cuda_fp16.h>
#include <cstddef>
#include <cstdint>

#define BB 16
#define TT 2048
#define CC 1024
#define HH 64
#define MM (BB*TT)   // 32768 rows

// fp16 scratch for projected Q,K,V (Q pre-scaled by C^-0.5 * log2(e))
__device__ __align__(256) __half g_Q[(size_t)MM*HH];
__device__ __align__(256) __half g_K[(size_t)MM*HH];
__device__ __align__(256) __half g_V[(size_t)MM*HH];

// ---------------------------------------------------------------------------
// helpers
// ---------------------------------------------------------------------------
__device__ __forceinline__ uint32_t smem_u32(const void* p) {
    return (uint32_t)__cvta_generic_to_shared(p);
}

__device__ __forceinline__ void ldsm4(uint32_t addr, unsigned& r0, unsigned& r1,
                                      unsigned& r2, unsigned& r3) {
    asm volatile("ldmatrix.sync.aligned.m8n8.x4.shared.b16 {%0,%1,%2,%3}, [%4];"
                 : "=r"(r0), "=r"(r1), "=r"(r2), "=r"(r3) : "r"(addr));
}

__device__ __forceinline__ void ldsm4t(uint32_t addr, unsigned& r0, unsigned& r1,
                                       unsigned& r2, unsigned& r3) {
    asm volatile("ldmatrix.sync.aligned.m8n8.x4.trans.shared.b16 {%0,%1,%2,%3}, [%4];"
                 : "=r"(r0), "=r"(r1), "=r"(r2), "=r"(r3) : "r"(addr));
}

__device__ __forceinline__ void mma16816(float* d, const unsigned* a,
                                         unsigned b0, unsigned b1, const float* c) {
    asm volatile(
        "mma.sync.aligned.m16n8k16.row.col.f32.f16.f16.f32 "
        "{%0,%1,%2,%3}, {%4,%5,%6,%7}, {%8,%9}, {%10,%11,%12,%13};"
        : "=f"(d[0]), "=f"(d[1]), "=f"(d[2]), "=f"(d[3])
        : "r"(a[0]), "r"(a[1]), "r"(a[2]), "r"(a[3]),
          "r"(b0), "r"(b1),
          "f"(c[0]), "f"(c[1]), "f"(c[2]), "f"(c[3]));
}

__device__ __forceinline__ float ex2(float x) {
    float y;
    asm("ex2.approx.ftz.f32 %0, %1;" : "=f"(y) : "f"(x));
    return y;
}

__device__ __forceinline__ void cp16(uint32_t dst, const void* src) {
    asm volatile("cp.async.cg.shared.global [%0], [%1], 16;" :: "r"(dst), "l"(src));
}
#define CP_COMMIT() asm volatile("cp.async.commit_group;")
#define CP_WAIT(N)  asm volatile("cp.async.wait_group %0;" :: "n"(N))

__device__ __forceinline__ unsigned h2u(__half2 h) {
    return *reinterpret_cast<unsigned*>(&h);
}

// ---------------------------------------------------------------------------
// Kernel 1: fused QKV projection (R9-proven version).
// fp16 MMA + ldmatrix + register double-buffer of x and W.
// CTA: 256 thr (8 warps: 4m x 2n), tile 64m x 192n, BK=32.
// ---------------------------------------------------------------------------
__global__ __launch_bounds__(256, 2) void qkv_kernel(
    const float* __restrict__ x,
    const float* __restrict__ Wq,
    const float* __restrict__ Wk,
    const float* __restrict__ Wv)
{
    __shared__ __half As[64][40];    // [m][k]
    __shared__ __half Bs[32][200];   // [k][n]  n = 3*64 + pad 8

    const int tid  = threadIdx.x;
    const int lane = tid & 31;
    const int wid  = tid >> 5;
    const int wm   = wid & 3;        // m strip of 16
    const int wn   = wid >> 2;       // n half of 96
    const int sub  = lane >> 3;
    const int rr   = lane & 7;
    const int g    = lane >> 2;
    const int t    = lane & 3;
    const int m0   = blockIdx.x * 64;

    const float* Ws[3] = {Wq, Wk, Wv};

    // register staging
    float4 ax[2], bw[6];
    const int a_row = (tid >> 3), a_c4 = (tid & 7);    // +i*32 rows
    const int b_row = (tid >> 4), b_c4 = (tid & 15);   // +j*16 rows

    float acc[12][4];
    #pragma unroll
    for (int nt = 0; nt < 12; nt++)
        #pragma unroll
        for (int e = 0; e < 4; e++) acc[nt][e] = 0.f;

    // prologue: load k0=0 tile into regs
    #pragma unroll
    for (int i = 0; i < 2; i++)
        ax[i] = *(const float4*)&x[(size_t)(m0 + a_row + i * 32) * CC + a_c4 * 4];
    #pragma unroll
    for (int mat = 0; mat < 3; mat++)
        #pragma unroll
        for (int j = 0; j < 2; j++)
            bw[mat * 2 + j] = *(const float4*)&Ws[mat][(size_t)(b_row + j * 16) * HH + b_c4 * 4];

    for (int k0 = 0; k0 < CC; k0 += 32) {
        // store staged regs -> smem
        #pragma unroll
        for (int i = 0; i < 2; i++) {
            __half2* p = (__half2*)&As[a_row + i * 32][a_c4 * 4];
            p[0] = __floats2half2_rn(ax[i].x, ax[i].y);
            p[1] = __floats2half2_rn(ax[i].z, ax[i].w);
        }
        #pragma unroll
        for (int mat = 0; mat < 3; mat++)
            #pragma unroll
            for (int j = 0; j < 2; j++) {
                float4 v = bw[mat * 2 + j];
                __half2* p = (__half2*)&Bs[b_row + j * 16][mat * 64 + b_c4 * 4];
                p[0] = __floats2half2_rn(v.x, v.y);
                p[1] = __floats2half2_rn(v.z, v.w);
            }
        __syncthreads();

        // issue next tile's global loads (overlap with MMA below)
        if (k0 + 32 < CC) {
            #pragma unroll
            for (int i = 0; i < 2; i++)
                ax[i] = *(const float4*)&x[(size_t)(m0 + a_row + i * 32) * CC
                                           + k0 + 32 + a_c4 * 4];
            #pragma unroll
            for (int mat = 0; mat < 3; mat++)
                #pragma unroll
                for (int j = 0; j < 2; j++)
                    bw[mat * 2 + j] = *(const float4*)
                        &Ws[mat][(size_t)(k0 + 32 + b_row + j * 16) * HH + b_c4 * 4];
        }

        // compute
        #pragma unroll
        for (int kt = 0; kt < 2; kt++) {
            unsigned a[4];
            uint32_t ad = smem_u32(&As[wm * 16 + (sub & 1) * 8 + rr]
                                      [kt * 16 + (sub >> 1) * 8]);
            ldsm4(ad, a[0], a[1], a[2], a[3]);
            #pragma unroll
            for (int p = 0; p < 6; p++) {
                unsigned b0, b1, b2, b3;
                uint32_t bd = smem_u32(&Bs[kt * 16 + (sub & 1) * 8 + rr]
                                          [wn * 96 + p * 16 + (sub >> 1) * 8]);
                ldsm4t(bd, b0, b1, b2, b3);
                mma16816(acc[2 * p    ], a, b0, b1, acc[2 * p    ]);
                mma16816(acc[2 * p + 1], a, b2, b3, acc[2 * p + 1]);
            }
        }
        __syncthreads();
    }

    // epilogue: fp16 stores (Q pre-scaled)
    const float QS = 0.03125f * 1.44269504f;
    #pragma unroll
    for (int nt = 0; nt < 12; nt++) {
        int n = wn * 96 + nt * 8 + 2 * t;
        int mat = n >> 6, col = n & 63;
        __half* O = (mat == 0) ? g_Q : (mat == 1) ? g_K : g_V;
        float sc = (mat == 0) ? QS : 1.f;
        int row = m0 + wm * 16 + g;
        *(__half2*)&O[(size_t)row * HH + col] =
            __floats2half2_rn(acc[nt][0] * sc, acc[nt][1] * sc);
        *(__half2*)&O[(size_t)(row + 8) * HH + col] =
            __floats2half2_rn(acc[nt][2] * sc, acc[nt][3] * sc);
    }
}

// ---------------------------------------------------------------------------
// Kernel 2: causal flash attention. CTA: 128 thr (4 warps), BM=64, BN=64,
// register-resident P, cp.async double-buffered K/V.
// grid (32, 16); it = 31 - blockIdx.x (heavy tiles launch first).
// All 512 CTAs co-resident at up to 4 CTAs/SM.
// ---------------------------------------------------------------------------
__global__ __launch_bounds__(128, 4) void attn_kernel(float* __restrict__ out)
{
    __shared__ __half Qs[64][72];
    __shared__ __half Ks[2][64][72];
    __shared__ __half Vs[2][64][72];

    const int tid  = threadIdx.x;
    const int lane = tid & 31;
    const int wid  = tid >> 5;        // q rows [16w, 16w+16)
    const int sub  = lane >> 3;
    const int rr   = lane & 7;
    const int g    = lane >> 2;
    const int t    = lane & 3;
    const int b    = blockIdx.y;
    const int it   = 31 - (int)blockIdx.x;     // heavy first

    const size_t base = (size_t)b * TT * HH;
    const int row0 = wid * 16;
    const int qrow = row0 + g;

    const int kv_r = tid >> 3;
    const int kv_c = tid & 7;

    // stage 0 K/V via cp.async
    {
        const size_t ga = base + (size_t)kv_r * HH + kv_c * 8;
        #pragma unroll
        for (int i = 0; i < 4; i++) {
            cp16(smem_u32(&Ks[0][kv_r + i * 16][kv_c * 8]),
                 &g_K[ga + (size_t)i * 16 * HH]);
            cp16(smem_u32(&Vs[0][kv_r + i * 16][kv_c * 8]),
                 &g_V[ga + (size_t)i * 16 * HH]);
        }
    }
    CP_COMMIT();

    // load Q tile
    #pragma unroll
    for (int i = 0; i < 4; i++) {
        int idx = tid + i * 128;
        int r = idx >> 3, c = idx & 7;
        *(uint4*)&Qs[r][c * 8] =
            *(const uint4*)&g_Q[base + (size_t)(it * 64 + r) * HH + c * 8];
    }
    __syncthreads();

    unsigned aq[4][4];
    #pragma unroll
    for (int kt = 0; kt < 4; kt++) {
        uint32_t ad = smem_u32(&Qs[row0 + (sub & 1) * 8 + rr]
                                  [kt * 16 + (sub >> 1) * 8]);
        ldsm4(ad, aq[kt][0], aq[kt][1], aq[kt][2], aq[kt][3]);
    }

    float o[8][4];
    #pragma unroll
    for (int nt = 0; nt < 8; nt++)
        #pragma unroll
        for (int e = 0; e < 4; e++) o[nt][e] = 0.f;
    float m0r = -1e30f, m1r = -1e30f, l0r = 0.f, l1r = 0.f;

    for (int jt = 0; jt <= it; jt++) {
        const int cur = jt & 1;

        if (jt < it) {   // prefetch next stage
            const size_t ga = base + (size_t)((jt + 1) * 64 + kv_r) * HH + kv_c * 8;
            #pragma unroll
            for (int i = 0; i < 4; i++) {
                cp16(smem_u32(&Ks[cur ^ 1][kv_r + i * 16][kv_c * 8]),
                     &g_K[ga + (size_t)i * 16 * HH]);
                cp16(smem_u32(&Vs[cur ^ 1][kv_r + i * 16][kv_c * 8]),
                     &g_V[ga + (size_t)i * 16 * HH]);
            }
            CP_COMMIT();
            CP_WAIT(1);
        } else {
            CP_WAIT(0);
        }
        __syncthreads();

        // S = Q @ K^T
        float s[8][4];
        #pragma unroll
        for (int nt = 0; nt < 8; nt++)
            #pragma unroll
            for (int e = 0; e < 4; e++) s[nt][e] = 0.f;

        #pragma unroll
        for (int kt = 0; kt < 4; kt++) {
            #pragma unroll
            for (int p = 0; p < 4; p++) {
                unsigned b0, b1, b2, b3;
                uint32_t kd = smem_u32(&Ks[cur][p * 16 + (sub >> 1) * 8 + rr]
                                          [kt * 16 + (sub & 1) * 8]);
                ldsm4(kd, b0, b1, b2, b3);
                mma16816(s[2 * p    ], aq[kt], b0, b1, s[2 * p    ]);
                mma16816(s[2 * p + 1], aq[kt], b2, b3, s[2 * p + 1]);
            }
        }

        // causal mask (diagonal tile only)
        if (jt == it) {
            #pragma unroll
            for (int nt = 0; nt < 8; nt++) {
                int c = nt * 8 + 2 * t;
                if (c     > qrow    ) s[nt][0] = -1e30f;
                if (c + 1 > qrow    ) s[nt][1] = -1e30f;
                if (c     > qrow + 8) s[nt][2] = -1e30f;
                if (c + 1 > qrow + 8) s[nt][3] = -1e30f;
            }
        }

        // online softmax (base-2; Q pre-scaled by log2 e)
        float mx0 = -1e30f, mx1 = -1e30f;
        #pragma unroll
        for (int nt = 0; nt < 8; nt++) {
            mx0 = fmaxf(mx0, fmaxf(s[nt][0], s[nt][1]));
            mx1 = fmaxf(mx1, fmaxf(s[nt][2], s[nt][3]));
        }
        mx0 = fmaxf(mx0, __shfl_xor_sync(0xffffffffu, mx0, 1));
        mx0 = fmaxf(mx0, __shfl_xor_sync(0xffffffffu, mx0, 2));
        mx1 = fmaxf(mx1, __shfl_xor_sync(0xffffffffu, mx1, 1));
        mx1 = fmaxf(mx1, __shfl_xor_sync(0xffffffffu, mx1, 2));

        float mn0 = fmaxf(m0r, mx0), mn1 = fmaxf(m1r, mx1);
        float al0 = ex2(m0r - mn0), al1 = ex2(m1r - mn1);
        float sum0 = 0.f, sum1 = 0.f;
        __half2 ph0[8], ph1[8];
        #pragma unroll
        for (int nt = 0; nt < 8; nt++) {
            s[nt][0] = ex2(s[nt][0] - mn0);
            s[nt][1] = ex2(s[nt][1] - mn0);
            s[nt][2] = ex2(s[nt][2] - mn1);
            s[nt][3] = ex2(s[nt][3] - mn1);
            sum0 += s[nt][0] + s[nt][1];
            sum1 += s[nt][2] + s[nt][3];
            ph0[nt] = __floats2half2_rn(s[nt][0], s[nt][1]);
            ph1[nt] = __floats2half2_rn(s[nt][2], s[nt][3]);
        }
        sum0 += __shfl_xor_sync(0xffffffffu, sum0, 1);
        sum0 += __shfl_xor_sync(0xffffffffu, sum0, 2);
        sum1 += __shfl_xor_sync(0xffffffffu, sum1, 1);
        sum1 += __shfl_xor_sync(0xffffffffu, sum1, 2);
        m0r = mn0; m1r = mn1;
        l0r = l0r * al0 + sum0;
        l1r = l1r * al1 + sum1;
        #pragma unroll
        for (int nt = 0; nt < 8; nt++) {
            o[nt][0] *= al0; o[nt][1] *= al0;
            o[nt][2] *= al1; o[nt][3] *= al1;
        }

        // O += P @ V   (P register-resident: C-frag == A-frag layout)
        #pragma unroll
        for (int kt = 0; kt < 4; kt++) {
            unsigned pa[4] = { h2u(ph0[2 * kt]),     h2u(ph1[2 * kt]),
                               h2u(ph0[2 * kt + 1]), h2u(ph1[2 * kt + 1]) };
            #pragma unroll
            for (int p = 0; p < 4; p++) {
                unsigned v0, v1, v2, v3;
                uint32_t vd = smem_u32(&Vs[cur][kt * 16 + (sub & 1) * 8 + rr]
                                          [p * 16 + (sub >> 1) * 8]);
                ldsm4t(vd, v0, v1, v2, v3);
                mma16816(o[2 * p    ], pa, v0, v1, o[2 * p    ]);
                mma16816(o[2 * p + 1], pa, v2, v3, o[2 * p + 1]);
            }
        }
        __syncthreads();   // all warps done with buf[cur] before refill
    }

    // epilogue
    float inv0 = 1.f / l0r, inv1 = 1.f / l1r;
    int r0 = it * 64 + qrow;
    #pragma unroll
    for (int nt = 0; nt < 8; nt++) {
        int c = nt * 8 + 2 * t;
        float2 v0 = {o[nt][0] * inv0, o[nt][1] * inv0};
        float2 v1 = {o[nt][2] * inv1, o[nt][3] * inv1};
        *(float2*)&out[base + (size_t)r0 * HH + c]       = v0;
        *(float2*)&out[base + (size_t)(r0 + 8) * HH + c] = v1;
    }
}

// ---------------------------------------------------------------------------
extern "C" void kernel_launch(void* const* d_in, const int* in_sizes, int n_in,
                              void* d_out, int out_size)
{
    const float* x  = (const float*)d_in[0];
    const float* Wq = (const float*)d_in[1];
    const float* Wk = (const float*)d_in[2];
    const float* Wv = (const float*)d_in[3];
    float* out = (float*)d_out;

    qkv_kernel<<<MM / 64, 256>>>(x, Wq, Wk, Wv);
    attn_kernel<<<dim3(32, BB), 128>>>(out);
}

// round 14
// speedup vs baseline: 1.3873x; 1.1499x over previous
#include <cuda_runtime.h>
#include <cuda_fp16.h>
#include <cstddef>
#include <cstdint>

#define BB 16
#define TT 2048
#define CC 1024
#define HH 64
#define MM (BB*TT)   // 32768 rows

// fp16 scratch (Q pre-scaled by C^-0.5 * log2(e))
__device__ __align__(256) __half g_Q[(size_t)MM*HH];
__device__ __align__(256) __half g_K[(size_t)MM*HH];
__device__ __align__(256) __half g_V[(size_t)MM*HH];
__device__ __align__(256) __half g_Wh[(size_t)CC*192];   // packed [k][Wq|Wk|Wv]

// ---------------------------------------------------------------------------
// helpers
// ---------------------------------------------------------------------------
__device__ __forceinline__ uint32_t smem_u32(const void* p) {
    return (uint32_t)__cvta_generic_to_shared(p);
}

__device__ __forceinline__ void ldsm4(uint32_t addr, unsigned& r0, unsigned& r1,
                                      unsigned& r2, unsigned& r3) {
    asm volatile("ldmatrix.sync.aligned.m8n8.x4.shared.b16 {%0,%1,%2,%3}, [%4];"
                 : "=r"(r0), "=r"(r1), "=r"(r2), "=r"(r3) : "r"(addr));
}

__device__ __forceinline__ void ldsm4t(uint32_t addr, unsigned& r0, unsigned& r1,
                                       unsigned& r2, unsigned& r3) {
    asm volatile("ldmatrix.sync.aligned.m8n8.x4.trans.shared.b16 {%0,%1,%2,%3}, [%4];"
                 : "=r"(r0), "=r"(r1), "=r"(r2), "=r"(r3) : "r"(addr));
}

__device__ __forceinline__ void mma16816(float* d, const unsigned* a,
                                         unsigned b0, unsigned b1, const float* c) {
    asm volatile(
        "mma.sync.aligned.m16n8k16.row.col.f32.f16.f16.f32 "
        "{%0,%1,%2,%3}, {%4,%5,%6,%7}, {%8,%9}, {%10,%11,%12,%13};"
        : "=f"(d[0]), "=f"(d[1]), "=f"(d[2]), "=f"(d[3])
        : "r"(a[0]), "r"(a[1]), "r"(a[2]), "r"(a[3]),
          "r"(b0), "r"(b1),
          "f"(c[0]), "f"(c[1]), "f"(c[2]), "f"(c[3]));
}

__device__ __forceinline__ float ex2(float x) {
    float y;
    asm("ex2.approx.ftz.f32 %0, %1;" : "=f"(y) : "f"(x));
    return y;
}

__device__ __forceinline__ void cp16(uint32_t dst, const void* src) {
    asm volatile("cp.async.cg.shared.global [%0], [%1], 16;" :: "r"(dst), "l"(src));
}
#define CP_COMMIT() asm volatile("cp.async.commit_group;")
#define CP_WAIT(N)  asm volatile("cp.async.wait_group %0;" :: "n"(N))

__device__ __forceinline__ unsigned h2u(__half2 h) {
    return *reinterpret_cast<unsigned*>(&h);
}

// ---------------------------------------------------------------------------
// Kernel 0: pack Wq|Wk|Wv -> fp16 g_Wh[k][192], vectorized (8 elems/thread).
// ---------------------------------------------------------------------------
__global__ __launch_bounds__(256) void wprep_kernel(
    const float* __restrict__ Wq,
    const float* __restrict__ Wk,
    const float* __restrict__ Wv)
{
    int c8 = blockIdx.x * 256 + threadIdx.x;       // chunk of 8 halves
    int k = c8 / 24, n = (c8 % 24) * 8;            // n in [0,192), 8-aligned
    int mat = n >> 6, col = n & 63;                // chunk stays within one mat
    const float* W = (mat == 0) ? Wq : (mat == 1) ? Wk : Wv;
    float4 v0 = *(const float4*)&W[(size_t)k * HH + col];
    float4 v1 = *(const float4*)&W[(size_t)k * HH + col + 4];
    __half2 h[4] = { __floats2half2_rn(v0.x, v0.y), __floats2half2_rn(v0.z, v0.w),
                     __floats2half2_rn(v1.x, v1.y), __floats2half2_rn(v1.z, v1.w) };
    *(uint4*)&g_Wh[(size_t)k * 192 + n] = *(uint4*)h;
}

// ---------------------------------------------------------------------------
// Kernel 1: fused QKV projection.  fp16 MMA + ldmatrix.
// CTA: 256 thr (8 warps: 4m x 2n), tile 64m x 192n, BK=32.
// Double-buffered smem (1 barrier/iter); x reg-staged fp32, W reg-staged fp16.
// ---------------------------------------------------------------------------
__global__ __launch_bounds__(256, 2) void qkv_kernel(const float* __restrict__ x)
{
    __shared__ __half As[2][64][40];     // [m][k]
    __shared__ __half Bs[2][32][200];    // [k][n]  n=192 + pad 8

    const int tid  = threadIdx.x;
    const int lane = tid & 31;
    const int wid  = tid >> 5;
    const int wm   = wid & 3;        // m strip of 16
    const int wn   = wid >> 2;       // n half of 96
    const int sub  = lane >> 3;
    const int rr   = lane & 7;
    const int g    = lane >> 2;
    const int t    = lane & 3;
    const int m0   = blockIdx.x * 64;

    // staging registers
    float4 ax[2];                    // x: rows a_row, a_row+32
    uint4  wb[3];                    // W fp16: 3 chunks of 8 halves
    const int a_row = tid >> 3, a_c4 = tid & 7;
    int w_row[3], w_n[3];
    #pragma unroll
    for (int j = 0; j < 3; j++) {
        int i = tid + j * 256;
        w_row[j] = i / 24; w_n[j] = (i % 24) * 8;
    }

    float acc[12][4];
    #pragma unroll
    for (int nt = 0; nt < 12; nt++)
        #pragma unroll
        for (int e = 0; e < 4; e++) acc[nt][e] = 0.f;

    // ---- prologue: tile 0 -> smem[0]; tile 1 -> regs
    #pragma unroll
    for (int i = 0; i < 2; i++)
        ax[i] = *(const float4*)&x[(size_t)(m0 + a_row + i * 32) * CC + a_c4 * 4];
    #pragma unroll
    for (int j = 0; j < 3; j++)
        wb[j] = *(const uint4*)&g_Wh[(size_t)w_row[j] * 192 + w_n[j]];

    #pragma unroll
    for (int i = 0; i < 2; i++) {
        __half2* p = (__half2*)&As[0][a_row + i * 32][a_c4 * 4];
        p[0] = __floats2half2_rn(ax[i].x, ax[i].y);
        p[1] = __floats2half2_rn(ax[i].z, ax[i].w);
    }
    #pragma unroll
    for (int j = 0; j < 3; j++)
        *(uint4*)&Bs[0][w_row[j]][w_n[j]] = wb[j];

    #pragma unroll
    for (int i = 0; i < 2; i++)
        ax[i] = *(const float4*)&x[(size_t)(m0 + a_row + i * 32) * CC + 32 + a_c4 * 4];
    #pragma unroll
    for (int j = 0; j < 3; j++)
        wb[j] = *(const uint4*)&g_Wh[(size_t)(32 + w_row[j]) * 192 + w_n[j]];
    __syncthreads();

    for (int k0 = 0; k0 < CC; k0 += 32) {
        const int c = (k0 >> 5) & 1;

        // store staged tile (k0+32) into buf c^1, then load tile k0+64
        if (k0 + 32 < CC) {
            #pragma unroll
            for (int i = 0; i < 2; i++) {
                __half2* p = (__half2*)&As[c ^ 1][a_row + i * 32][a_c4 * 4];
                p[0] = __floats2half2_rn(ax[i].x, ax[i].y);
                p[1] = __floats2half2_rn(ax[i].z, ax[i].w);
            }
            #pragma unroll
            for (int j = 0; j < 3; j++)
                *(uint4*)&Bs[c ^ 1][w_row[j]][w_n[j]] = wb[j];

            if (k0 + 64 < CC) {
                #pragma unroll
                for (int i = 0; i < 2; i++)
                    ax[i] = *(const float4*)&x[(size_t)(m0 + a_row + i * 32) * CC
                                               + k0 + 64 + a_c4 * 4];
                #pragma unroll
                for (int j = 0; j < 3; j++)
                    wb[j] = *(const uint4*)&g_Wh[(size_t)(k0 + 64 + w_row[j]) * 192
                                                 + w_n[j]];
            }
        }

        // compute from buf c
        #pragma unroll
        for (int kt = 0; kt < 2; kt++) {
            unsigned a[4];
            uint32_t ad = smem_u32(&As[c][wm * 16 + (sub & 1) * 8 + rr]
                                      [kt * 16 + (sub >> 1) * 8]);
            ldsm4(ad, a[0], a[1], a[2], a[3]);
            #pragma unroll
            for (int p = 0; p < 6; p++) {
                unsigned b0, b1, b2, b3;
                uint32_t bd = smem_u32(&Bs[c][kt * 16 + (sub & 1) * 8 + rr]
                                          [wn * 96 + p * 16 + (sub >> 1) * 8]);
                ldsm4t(bd, b0, b1, b2, b3);
                mma16816(acc[2 * p    ], a, b0, b1, acc[2 * p    ]);
                mma16816(acc[2 * p + 1], a, b2, b3, acc[2 * p + 1]);
            }
        }
        __syncthreads();
    }

    // epilogue: fp16 stores (Q pre-scaled)
    const float QS = 0.03125f * 1.44269504f;
    #pragma unroll
    for (int nt = 0; nt < 12; nt++) {
        int n = wn * 96 + nt * 8 + 2 * t;
        int mat = n >> 6, col = n & 63;
        __half* O = (mat == 0) ? g_Q : (mat == 1) ? g_K : g_V;
        float sc = (mat == 0) ? QS : 1.f;
        int row = m0 + wm * 16 + g;
        *(__half2*)&O[(size_t)row * HH + col] =
            __floats2half2_rn(acc[nt][0] * sc, acc[nt][1] * sc);
        *(__half2*)&O[(size_t)(row + 8) * HH + col] =
            __floats2half2_rn(acc[nt][2] * sc, acc[nt][3] * sc);
    }
}

// ---------------------------------------------------------------------------
// Kernel 2: causal flash attention (R9-proven). CTA: 128 thr (4 warps),
// BM=64, BN=64, register-resident P, cp.async double-buffered K/V.
// Each CTA processes q-tile pair (x, 31-x) -> uniform 33 kv-steps.
// ---------------------------------------------------------------------------
__global__ __launch_bounds__(128) void attn_kernel(float* __restrict__ out)
{
    __shared__ __half Qs[64][72];
    __shared__ __half Ks[2][64][72];
    __shared__ __half Vs[2][64][72];

    const int tid  = threadIdx.x;
    const int lane = tid & 31;
    const int wid  = tid >> 5;        // q rows [16w, 16w+16)
    const int sub  = lane >> 3;
    const int rr   = lane & 7;
    const int g    = lane >> 2;
    const int t    = lane & 3;
    const int b    = blockIdx.y;

    const size_t base = (size_t)b * TT * HH;
    const int row0 = wid * 16;
    const int qrow = row0 + g;

    const int kv_r = tid >> 3;
    const int kv_c = tid & 7;

    #pragma unroll
    for (int pass = 0; pass < 2; pass++) {
        const int it = (pass == 0) ? (int)blockIdx.x : (31 - (int)blockIdx.x);

        __syncthreads();   // smem free from previous pass

        // stage 0 K/V via cp.async
        {
            const size_t ga = base + (size_t)kv_r * HH + kv_c * 8;
            #pragma unroll
            for (int i = 0; i < 4; i++) {
                cp16(smem_u32(&Ks[0][kv_r + i * 16][kv_c * 8]),
                     &g_K[ga + (size_t)i * 16 * HH]);
                cp16(smem_u32(&Vs[0][kv_r + i * 16][kv_c * 8]),
                     &g_V[ga + (size_t)i * 16 * HH]);
            }
        }
        CP_COMMIT();

        // load Q tile
        #pragma unroll
        for (int i = 0; i < 4; i++) {
            int idx = tid + i * 128;
            int r = idx >> 3, c = idx & 7;
            *(uint4*)&Qs[r][c * 8] =
                *(const uint4*)&g_Q[base + (size_t)(it * 64 + r) * HH + c * 8];
        }
        __syncthreads();

        unsigned aq[4][4];
        #pragma unroll
        for (int kt = 0; kt < 4; kt++) {
            uint32_t ad = smem_u32(&Qs[row0 + (sub & 1) * 8 + rr]
                                      [kt * 16 + (sub >> 1) * 8]);
            ldsm4(ad, aq[kt][0], aq[kt][1], aq[kt][2], aq[kt][3]);
        }

        float o[8][4];
        #pragma unroll
        for (int nt = 0; nt < 8; nt++)
            #pragma unroll
            for (int e = 0; e < 4; e++) o[nt][e] = 0.f;
        float m0r = -1e30f, m1r = -1e30f, l0r = 0.f, l1r = 0.f;

        for (int jt = 0; jt <= it; jt++) {
            const int cur = jt & 1;

            if (jt < it) {   // prefetch next stage
                const size_t ga = base + (size_t)((jt + 1) * 64 + kv_r) * HH + kv_c * 8;
                #pragma unroll
                for (int i = 0; i < 4; i++) {
                    cp16(smem_u32(&Ks[cur ^ 1][kv_r + i * 16][kv_c * 8]),
                         &g_K[ga + (size_t)i * 16 * HH]);
                    cp16(smem_u32(&Vs[cur ^ 1][kv_r + i * 16][kv_c * 8]),
                         &g_V[ga + (size_t)i * 16 * HH]);
                }
                CP_COMMIT();
                CP_WAIT(1);
            } else {
                CP_WAIT(0);
            }
            __syncthreads();

            // S = Q @ K^T
            float s[8][4];
            #pragma unroll
            for (int nt = 0; nt < 8; nt++)
                #pragma unroll
                for (int e = 0; e < 4; e++) s[nt][e] = 0.f;

            #pragma unroll
            for (int kt = 0; kt < 4; kt++) {
                #pragma unroll
                for (int p = 0; p < 4; p++) {
                    unsigned b0, b1, b2, b3;
                    uint32_t kd = smem_u32(&Ks[cur][p * 16 + (sub >> 1) * 8 + rr]
                                              [kt * 16 + (sub & 1) * 8]);
                    ldsm4(kd, b0, b1, b2, b3);
                    mma16816(s[2 * p    ], aq[kt], b0, b1, s[2 * p    ]);
                    mma16816(s[2 * p + 1], aq[kt], b2, b3, s[2 * p + 1]);
                }
            }

            // causal mask (diagonal tile only)
            if (jt == it) {
                #pragma unroll
                for (int nt = 0; nt < 8; nt++) {
                    int c = nt * 8 + 2 * t;
                    if (c     > qrow    ) s[nt][0] = -1e30f;
                    if (c + 1 > qrow    ) s[nt][1] = -1e30f;
                    if (c     > qrow + 8) s[nt][2] = -1e30f;
                    if (c + 1 > qrow + 8) s[nt][3] = -1e30f;
                }
            }

            // online softmax (base-2; Q pre-scaled by log2 e)
            float mx0 = -1e30f, mx1 = -1e30f;
            #pragma unroll
            for (int nt = 0; nt < 8; nt++) {
                mx0 = fmaxf(mx0, fmaxf(s[nt][0], s[nt][1]));
                mx1 = fmaxf(mx1, fmaxf(s[nt][2], s[nt][3]));
            }
            mx0 = fmaxf(mx0, __shfl_xor_sync(0xffffffffu, mx0, 1));
            mx0 = fmaxf(mx0, __shfl_xor_sync(0xffffffffu, mx0, 2));
            mx1 = fmaxf(mx1, __shfl_xor_sync(0xffffffffu, mx1, 1));
            mx1 = fmaxf(mx1, __shfl_xor_sync(0xffffffffu, mx1, 2));

            float mn0 = fmaxf(m0r, mx0), mn1 = fmaxf(m1r, mx1);
            float al0 = ex2(m0r - mn0), al1 = ex2(m1r - mn1);
            float sum0 = 0.f, sum1 = 0.f;
            __half2 ph0[8], ph1[8];
            #pragma unroll
            for (int nt = 0; nt < 8; nt++) {
                s[nt][0] = ex2(s[nt][0] - mn0);
                s[nt][1] = ex2(s[nt][1] - mn0);
                s[nt][2] = ex2(s[nt][2] - mn1);
                s[nt][3] = ex2(s[nt][3] - mn1);
                sum0 += s[nt][0] + s[nt][1];
                sum1 += s[nt][2] + s[nt][3];
                ph0[nt] = __floats2half2_rn(s[nt][0], s[nt][1]);
                ph1[nt] = __floats2half2_rn(s[nt][2], s[nt][3]);
            }
            sum0 += __shfl_xor_sync(0xffffffffu, sum0, 1);
            sum0 += __shfl_xor_sync(0xffffffffu, sum0, 2);
            sum1 += __shfl_xor_sync(0xffffffffu, sum1, 1);
            sum1 += __shfl_xor_sync(0xffffffffu, sum1, 2);
            m0r = mn0; m1r = mn1;
            l0r = l0r * al0 + sum0;
            l1r = l1r * al1 + sum1;
            #pragma unroll
            for (int nt = 0; nt < 8; nt++) {
                o[nt][0] *= al0; o[nt][1] *= al0;
                o[nt][2] *= al1; o[nt][3] *= al1;
            }

            // O += P @ V   (P register-resident: C-frag == A-frag layout)
            #pragma unroll
            for (int kt = 0; kt < 4; kt++) {
                unsigned pa[4] = { h2u(ph0[2 * kt]),     h2u(ph1[2 * kt]),
                                   h2u(ph0[2 * kt + 1]), h2u(ph1[2 * kt + 1]) };
                #pragma unroll
                for (int p = 0; p < 4; p++) {
                    unsigned v0, v1, v2, v3;
                    uint32_t vd = smem_u32(&Vs[cur][kt * 16 + (sub & 1) * 8 + rr]
                                              [p * 16 + (sub >> 1) * 8]);
                    ldsm4t(vd, v0, v1, v2, v3);
                    mma16816(o[2 * p    ], pa, v0, v1, o[2 * p    ]);
                    mma16816(o[2 * p + 1], pa, v2, v3, o[2 * p + 1]);
                }
            }
            __syncthreads();   // all warps done with buf[cur] before refill
        }

        // epilogue
        float inv0 = 1.f / l0r, inv1 = 1.f / l1r;
        int r0 = it * 64 + qrow;
        #pragma unroll
        for (int nt = 0; nt < 8; nt++) {
            int c = nt * 8 + 2 * t;
            float2 v0 = {o[nt][0] * inv0, o[nt][1] * inv0};
            float2 v1 = {o[nt][2] * inv1, o[nt][3] * inv1};
            *(float2*)&out[base + (size_t)r0 * HH + c]       = v0;
            *(float2*)&out[base + (size_t)(r0 + 8) * HH + c] = v1;
        }
    }
}

// ---------------------------------------------------------------------------
extern "C" void kernel_launch(void* const* d_in, const int* in_sizes, int n_in,
                              void* d_out, int out_size)
{
    const float* x  = (const float*)d_in[0];
    const float* Wq = (const float*)d_in[1];
    const float* Wk = (const float*)d_in[2];
    const float* Wv = (const float*)d_in[3];
    float* out = (float*)d_out;

    wprep_kernel<<<CC * 192 / 8 / 256, 256>>>(Wq, Wk, Wv);
    qkv_kernel<<<MM / 64, 256>>>(x);
    attn_kernel<<<dim3(16, BB), 128>>>(out);
}